// round 17
// baseline (speedup 1.0000x reference)
#include <cuda_runtime.h>
#include <math.h>

// CapsuleLayer dynamic routing v14: v6 (best, 219.2us) with k_esum folded into
// the CONSUMER (k_squash): each squash block redundantly reduces g_epart
// (288x32, L2-broadcast) into smem before the squash loop. No fences/atomics.

#define BB 64
#define NN 2304
#define CC 32
#define OO 16
#define II 8
#define CO 512
#define WROW 4096     // C*O*I floats per n
#define NCHUNK 72
#define NPC 32        // NN / NCHUNK
#define BG 16         // batch rows per block
#define BP 8          // b-pairs per block
#define NBG 4

__device__ float g_spart[(size_t)NCHUNK * BB * CO];  // 9.4 MB
__device__ float g_v[BB * CO];
__device__ float g_bupd[NBG * NN * CC];
__device__ float g_b[NN * CC];
__device__ float g_e[NN * CC];
__device__ float g_epart[288 * CC];

typedef unsigned long long u64;

__device__ __forceinline__ u64 pk2(float lo, float hi) {
    u64 r; asm("mov.b64 %0,{%1,%2};" : "=l"(r) : "f"(lo), "f"(hi)); return r;
}
__device__ __forceinline__ float2 unpk(u64 v) {
    float2 r; asm("mov.b64 {%0,%1},%2;" : "=f"(r.x), "=f"(r.y) : "l"(v)); return r;
}
__device__ __forceinline__ u64 ffma2(u64 a, u64 b, u64 c) {
    u64 d; asm("fma.rn.f32x2 %0,%1,%2,%3;" : "=l"(d) : "l"(a), "l"(b), "l"(c)); return d;
}
__device__ __forceinline__ u64 fmul2(u64 a, u64 b) {
    u64 d; asm("mul.rn.f32x2 %0,%1,%2;" : "=l"(d) : "l"(a), "l"(b)); return d;
}

// shared x tile: xs[ipair(4)][bp(8)][nn(32)] of ulonglong2 = 16KB
#define XS_LOAD(xs, x4, bg, n0, t)                                              \
    {                                                                            \
        int bp = (t) >> 5;                                                       \
        int nn = (t) & 31;                                                       \
        const float4* xp0 = (x4) + ((size_t)((bg) * BG + 2 * bp) * NN + ((n0) + nn)) * 2; \
        const float4* xp1 = (x4) + ((size_t)((bg) * BG + 2 * bp + 1) * NN + ((n0) + nn)) * 2; \
        float4 a0 = xp0[0], a1 = xp0[1];                                         \
        float4 c0 = xp1[0], c1 = xp1[1];                                         \
        xs[0][bp][nn] = make_ulonglong2(pk2(a0.x, c0.x), pk2(a0.y, c0.y));       \
        xs[1][bp][nn] = make_ulonglong2(pk2(a0.z, c0.z), pk2(a0.w, c0.w));       \
        xs[2][bp][nn] = make_ulonglong2(pk2(a1.x, c1.x), pk2(a1.y, c1.y));       \
        xs[3][bp][nn] = make_ulonglong2(pk2(a1.z, c1.z), pk2(a1.w, c1.w));       \
    }

// ---------------------------------------------------------------------------
// k_sj: s partials. block = (n-chunk of 32, b-group of 16); 256 threads.
// ---------------------------------------------------------------------------
__global__ __launch_bounds__(256, 2)
void k_sj(const float* __restrict__ x, const float* __restrict__ W, int use_e)
{
    const int chunk = blockIdx.x;
    const int bg    = blockIdx.y;
    const int t     = threadIdx.x;
    const int n0    = chunk * NPC;
    const int c     = t >> 3;

    __shared__ ulonglong2 xs[4][BP][NPC];   // 16KB
    __shared__ float es[NPC * CC];          // 4KB

    const float4* x4 = (const float4*)x;
    XS_LOAD(xs, x4, bg, n0, t);
    if (use_e) {
        for (int idx = t; idx < NPC * CC; idx += 256)
            es[idx] = g_e[(size_t)n0 * CC + idx];
    }
    __syncthreads();

    u64 acc0[BP], acc1[BP];
#pragma unroll
    for (int bp = 0; bp < BP; bp++) { acc0[bp] = 0ull; acc1[bp] = 0ull; }

    const float4* wp = (const float4*)(W + (size_t)n0 * WROW + (size_t)(2 * t) * II);
    float4 wa0 = wp[0], wa1 = wp[1], wb0 = wp[2], wb1 = wp[3];

    for (int nn = 0; nn < NPC; nn++) {
        float cw = use_e ? es[nn * CC + c] : (1.0f / (float)NN);
        u64 wc0[8], wc1[8];
        {
            float m;
            m = wa0.x * cw; wc0[0] = pk2(m, m);
            m = wa0.y * cw; wc0[1] = pk2(m, m);
            m = wa0.z * cw; wc0[2] = pk2(m, m);
            m = wa0.w * cw; wc0[3] = pk2(m, m);
            m = wa1.x * cw; wc0[4] = pk2(m, m);
            m = wa1.y * cw; wc0[5] = pk2(m, m);
            m = wa1.z * cw; wc0[6] = pk2(m, m);
            m = wa1.w * cw; wc0[7] = pk2(m, m);
            m = wb0.x * cw; wc1[0] = pk2(m, m);
            m = wb0.y * cw; wc1[1] = pk2(m, m);
            m = wb0.z * cw; wc1[2] = pk2(m, m);
            m = wb0.w * cw; wc1[3] = pk2(m, m);
            m = wb1.x * cw; wc1[4] = pk2(m, m);
            m = wb1.y * cw; wc1[5] = pk2(m, m);
            m = wb1.z * cw; wc1[6] = pk2(m, m);
            m = wb1.w * cw; wc1[7] = pk2(m, m);
        }
        if (nn + 1 < NPC) {
            const float4* wn = wp + (size_t)(nn + 1) * (WROW / 4);
            wa0 = wn[0]; wa1 = wn[1]; wb0 = wn[2]; wb1 = wn[3];
        }
#pragma unroll
        for (int bp = 0; bp < BP; bp++) {
            ulonglong2 x01 = xs[0][bp][nn];
            ulonglong2 x23 = xs[1][bp][nn];
            ulonglong2 x45 = xs[2][bp][nn];
            ulonglong2 x67 = xs[3][bp][nn];
            u64 a0 = acc0[bp], a1 = acc1[bp];
            a0 = ffma2(wc0[0], x01.x, a0); a1 = ffma2(wc1[0], x01.x, a1);
            a0 = ffma2(wc0[1], x01.y, a0); a1 = ffma2(wc1[1], x01.y, a1);
            a0 = ffma2(wc0[2], x23.x, a0); a1 = ffma2(wc1[2], x23.x, a1);
            a0 = ffma2(wc0[3], x23.y, a0); a1 = ffma2(wc1[3], x23.y, a1);
            a0 = ffma2(wc0[4], x45.x, a0); a1 = ffma2(wc1[4], x45.x, a1);
            a0 = ffma2(wc0[5], x45.y, a0); a1 = ffma2(wc1[5], x45.y, a1);
            a0 = ffma2(wc0[6], x67.x, a0); a1 = ffma2(wc1[6], x67.x, a1);
            a0 = ffma2(wc0[7], x67.y, a0); a1 = ffma2(wc1[7], x67.y, a1);
            acc0[bp] = a0; acc1[bp] = a1;
        }
    }

    float* sp = g_spart + ((size_t)chunk * BB + (size_t)bg * BG) * CO + 2 * t;
#pragma unroll
    for (int bp = 0; bp < BP; bp++) {
        float2 f0 = unpk(acc0[bp]);   // (s[b0,co0], s[b1,co0])
        float2 f1 = unpk(acc1[bp]);   // (s[b0,co1], s[b1,co1])
        *(float2*)(sp + (size_t)(2 * bp) * CO)     = make_float2(f0.x, f1.x);
        *(float2*)(sp + (size_t)(2 * bp + 1) * CO) = make_float2(f0.y, f1.y);
    }
}

// ---------------------------------------------------------------------------
// k_bupd: agreement partials; recompute t per n, dot with v (b-pair packed).
// ---------------------------------------------------------------------------
__global__ __launch_bounds__(256, 2)
void k_bupd(const float* __restrict__ x, const float* __restrict__ W)
{
    const int chunk = blockIdx.x;
    const int bg    = blockIdx.y;
    const int t     = threadIdx.x;
    const int n0    = chunk * NPC;

    __shared__ ulonglong2 xs[4][BP][NPC];   // 16KB

    const float4* x4 = (const float4*)x;
    XS_LOAD(xs, x4, bg, n0, t);
    __syncthreads();

    u64 vp0[BP], vp1[BP];
#pragma unroll
    for (int bp = 0; bp < BP; bp++) {
        const float* v0 = g_v + (size_t)(bg * BG + 2 * bp) * CO + 2 * t;
        const float* v1 = g_v + (size_t)(bg * BG + 2 * bp + 1) * CO + 2 * t;
        float2 a = *(const float2*)v0;   // (v[b0,co0], v[b0,co1])
        float2 b = *(const float2*)v1;
        vp0[bp] = pk2(a.x, b.x);         // (v[b0,co0], v[b1,co0])
        vp1[bp] = pk2(a.y, b.y);         // (v[b0,co1], v[b1,co1])
    }

    const float4* wp = (const float4*)(W + (size_t)n0 * WROW + (size_t)(2 * t) * II);
    float4 wa0 = wp[0], wa1 = wp[1], wb0 = wp[2], wb1 = wp[3];

    for (int nn = 0; nn < NPC; nn++) {
        u64 wd0[8], wd1[8];
        wd0[0] = pk2(wa0.x, wa0.x); wd0[1] = pk2(wa0.y, wa0.y);
        wd0[2] = pk2(wa0.z, wa0.z); wd0[3] = pk2(wa0.w, wa0.w);
        wd0[4] = pk2(wa1.x, wa1.x); wd0[5] = pk2(wa1.y, wa1.y);
        wd0[6] = pk2(wa1.z, wa1.z); wd0[7] = pk2(wa1.w, wa1.w);
        wd1[0] = pk2(wb0.x, wb0.x); wd1[1] = pk2(wb0.y, wb0.y);
        wd1[2] = pk2(wb0.z, wb0.z); wd1[3] = pk2(wb0.w, wb0.w);
        wd1[4] = pk2(wb1.x, wb1.x); wd1[5] = pk2(wb1.y, wb1.y);
        wd1[6] = pk2(wb1.z, wb1.z); wd1[7] = pk2(wb1.w, wb1.w);
        if (nn + 1 < NPC) {
            const float4* wn = wp + (size_t)(nn + 1) * (WROW / 4);
            wa0 = wn[0]; wa1 = wn[1]; wb0 = wn[2]; wb1 = wn[3];
        }
        u64 pacc = 0ull;
#pragma unroll
        for (int bp = 0; bp < BP; bp++) {
            ulonglong2 x01 = xs[0][bp][nn];
            ulonglong2 x23 = xs[1][bp][nn];
            ulonglong2 x45 = xs[2][bp][nn];
            ulonglong2 x67 = xs[3][bp][nn];
            u64 t0 = fmul2(wd0[0], x01.x);
            u64 t1 = fmul2(wd1[0], x01.x);
            t0 = ffma2(wd0[1], x01.y, t0); t1 = ffma2(wd1[1], x01.y, t1);
            t0 = ffma2(wd0[2], x23.x, t0); t1 = ffma2(wd1[2], x23.x, t1);
            t0 = ffma2(wd0[3], x23.y, t0); t1 = ffma2(wd1[3], x23.y, t1);
            t0 = ffma2(wd0[4], x45.x, t0); t1 = ffma2(wd1[4], x45.x, t1);
            t0 = ffma2(wd0[5], x45.y, t0); t1 = ffma2(wd1[5], x45.y, t1);
            t0 = ffma2(wd0[6], x67.x, t0); t1 = ffma2(wd1[6], x67.x, t1);
            t0 = ffma2(wd0[7], x67.y, t0); t1 = ffma2(wd1[7], x67.y, t1);
            pacc = ffma2(t0, vp0[bp], pacc);
            pacc = ffma2(t1, vp1[bp], pacc);
        }
        float2 pv = unpk(pacc);
        float p = pv.x + pv.y;
        p += __shfl_down_sync(0xffffffffu, p, 4, 8);
        p += __shfl_down_sync(0xffffffffu, p, 2, 8);
        p += __shfl_down_sync(0xffffffffu, p, 1, 8);
        if ((t & 7) == 0)
            g_bupd[(size_t)bg * (NN * CC) + (size_t)(n0 + nn) * CC + (t >> 3)] = p;
    }
}

// ---------------------------------------------------------------------------
// k_squash: (optional) redundant per-block reduction of g_epart -> sinv[32]
// in smem, then float2 partial reduce + squash. 128 blocks x 128 threads.
// ---------------------------------------------------------------------------
__global__ void k_squash(float* __restrict__ dout, int uniform, int final_pass)
{
    const int t = threadIdx.x;
    __shared__ float sred[128];
    __shared__ float sinv[CC];

    if (!uniform) {
        // reduce 288x32 epart: thread t -> c = t&31, row group = t>>5 (0..3)
        const int c   = t & 31;
        const int grp = t >> 5;
        float s = 0.0f;
        for (int r = grp; r < 288; r += 4)
            s += g_epart[r * 32 + c];
        sred[t] = s;
        __syncthreads();
        if (t < 32)
            sinv[t] = 1.0f / (sred[t] + sred[t + 32] + sred[t + 64] + sred[t + 96]);
        __syncthreads();
    }

    int id2 = blockIdx.x * 128 + t;   // 0..16383 (b*256 + co/2)
    const float2* sp = (const float2*)g_spart;
    float sx = 0.0f, sy = 0.0f;
#pragma unroll 8
    for (int ch = 0; ch < NCHUNK; ch++) {
        float2 p = sp[(size_t)ch * 16384 + id2];
        sx += p.x; sy += p.y;
    }
    int c = (id2 >> 3) & 31;
    float scale = uniform ? 1.0f : sinv[c];
    sx *= scale; sy *= scale;
    float2 v;
    v.x = sx * fabsf(sx) / (1.0f + sx * sx);
    v.y = sy * fabsf(sy) / (1.0f + sy * sy);
    if (final_pass) ((float2*)dout)[id2] = v;
    else            ((float2*)g_v)[id2]  = v;
}

// ---------------------------------------------------------------------------
// k_bcomb: combine 4 agreement partials, update b, e = exp(b), per-block
// partial e-sums per c. grid 288 x 256. (v6 version, proven.)
// ---------------------------------------------------------------------------
__global__ void k_bcomb(int iter0)
{
    const int t   = threadIdx.x;
    const int idx = blockIdx.x * 256 + t;     // n*32 + c

    float a = g_bupd[idx]
            + g_bupd[(size_t)NN * CC + idx]
            + g_bupd[(size_t)2 * NN * CC + idx]
            + g_bupd[(size_t)3 * NN * CC + idx];
    a *= (1.0f / (float)BB);

    float bb = iter0 ? a : (g_b[idx] + a);
    g_b[idx] = bb;
    float e = expf(bb);
    g_e[idx] = e;

    __shared__ float sred[256];
    sred[t] = e;
    __syncthreads();
    if (t < 32) {
        float s = 0.0f;
#pragma unroll
        for (int r = 0; r < 8; r++) s += sred[r * 32 + t];
        g_epart[blockIdx.x * 32 + t] = s;
    }
}

// ---------------------------------------------------------------------------
extern "C" void kernel_launch(void* const* d_in, const int* in_sizes, int n_in,
                              void* d_out, int out_size)
{
    const float* x = (const float*)d_in[0];   // [B, N, I]
    const float* W = (const float*)d_in[1];   // [N, C, O, I]
    float* out = (float*)d_out;               // [B, C, O, 1]

    dim3 g(NCHUNK, NBG);

    // iteration 0 (uniform weights 1/N inside k_sj)
    k_sj<<<g, 256>>>(x, W, 0);
    k_squash<<<128, 128>>>(out, 1, 0);
    k_bupd<<<g, 256>>>(x, W);
    k_bcomb<<<288, 256>>>(1);

    // iteration 1 (weights = exp(b); inv computed inside squash)
    k_sj<<<g, 256>>>(x, W, 1);
    k_squash<<<128, 128>>>(out, 0, 0);
    k_bupd<<<g, 256>>>(x, W);
    k_bcomb<<<288, 256>>>(0);

    // iteration 2 (final)
    k_sj<<<g, 256>>>(x, W, 1);
    k_squash<<<128, 128>>>(out, 0, 1);
}